// round 2
// baseline (speedup 1.0000x reference)
#include <cuda_runtime.h>
#include <cstdint>

// Problem constants (fixed by the dataset)
#define NN 100000
#define NE 800000
#define HD 64

// ---------------- device scratch (static: no allocation allowed) -------------
__device__ __align__(16) float g_tmp [(size_t)NN * HD];   // h = X @ W
__device__ __align__(16) float g_bufA[(size_t)NN * HD];   // layer ping buffer
__device__ int   g_deg [NN];
__device__ float g_dinv[NN];
__device__ int   g_off [NN];
__device__ int   g_pos [NN];
__device__ int   g_csr [NE + NN];
__device__ int   g_bsum[256];
__device__ int   g_is64;

// ---------------- edge dtype detection (int32 vs int64), device-side --------
__global__ void k_detect(const long long* __restrict__ ei64, int n) {
    if (threadIdx.x == 0 && blockIdx.x == 0) {
        int is64 = 1;
        #pragma unroll
        for (int k = 0; k < 16; k++) {
            long long v = ei64[k];            // safe: first 128B of buffer
            if (v < 0 || v >= (long long)n) { is64 = 0; break; }
        }
        g_is64 = is64;
    }
}

__device__ __forceinline__ int edge_at(const int* __restrict__ p32,
                                       const long long* __restrict__ p64,
                                       int idx) {
    return g_is64 ? (int)__ldg(&p64[idx]) : __ldg(&p32[idx]);
}

// ---------------- CSR construction ------------------------------------------
__global__ void k_init_deg(int n) {
    int i = blockIdx.x * blockDim.x + threadIdx.x;
    if (i < n) g_deg[i] = 1;                      // self-loop
}

__global__ void k_count(const int* __restrict__ e32,
                        const long long* __restrict__ e64, int E) {
    int e = blockIdx.x * blockDim.x + threadIdx.x;
    if (e < E) {
        int c = edge_at(e32, e64, E + e);         // col = destinations
        atomicAdd(&g_deg[c], 1);
    }
}

// block-local exclusive scan over deg (512/block) + dinv = rsqrt(deg)
__global__ void k_scanA(int n) {
    __shared__ int s[512];
    int i = blockIdx.x * 512 + threadIdx.x;
    int v = (i < n) ? g_deg[i] : 0;
    if (i < n) g_dinv[i] = rsqrtf((float)v);
    s[threadIdx.x] = v;
    __syncthreads();
    #pragma unroll
    for (int d = 1; d < 512; d <<= 1) {
        int t = (threadIdx.x >= d) ? s[threadIdx.x - d] : 0;
        __syncthreads();
        s[threadIdx.x] += t;
        __syncthreads();
    }
    if (i < n) g_off[i] = s[threadIdx.x] - v;     // exclusive within block
    if (threadIdx.x == 511) g_bsum[blockIdx.x] = s[511];
}

__global__ void k_scanB(int nb) {
    if (threadIdx.x == 0 && blockIdx.x == 0) {
        int run = 0;
        for (int b = 0; b < nb; b++) { int t = g_bsum[b]; g_bsum[b] = run; run += t; }
    }
}

__global__ void k_scanC(int n) {
    int i = blockIdx.x * blockDim.x + threadIdx.x;
    if (i < n) {
        int o = g_off[i] + g_bsum[i >> 9];
        g_off[i] = o;
        g_pos[i] = o;
    }
}

__global__ void k_fill(const int* __restrict__ e32,
                       const long long* __restrict__ e64, int E, int n) {
    int e = blockIdx.x * blockDim.x + threadIdx.x;
    if (e < E) {
        int r = edge_at(e32, e64, e);             // row = source
        int c = edge_at(e32, e64, E + e);         // col = destination
        int p = atomicAdd(&g_pos[c], 1);
        g_csr[p] = r;
    } else if (e < E + n) {
        int i = e - E;
        int p = atomicAdd(&g_pos[i], 1);
        g_csr[p] = i;                              // self-loop
    }
}

// ---------------- GEMM: Y[n,64] = X[n,64] @ W[64,64] (+bias) ----------------
// 64 rows/block, 128 threads, 8x4 register micro-tile, f32x2 packed FMA.
__global__ void __launch_bounds__(128) k_gemm64(
    const float* __restrict__ X, const float* __restrict__ W,
    const float* __restrict__ bias, float* __restrict__ Y,
    int n, int addBias)
{
    __shared__ float Xs[64][66];     // pad 66 -> conflict-free a-loads
    __shared__ float Ws[64][64];
    const int t = threadIdx.x;
    const int row0 = blockIdx.x * 64;

    // load W (4096 floats) via float4
    {
        const float4* W4 = (const float4*)W;
        float4* Ws4 = (float4*)Ws;
        #pragma unroll
        for (int i = t; i < 1024; i += 128) Ws4[i] = W4[i];
    }
    // load X tile (64 rows x 64 cols), zero-pad past n
    for (int i = t; i < 1024; i += 128) {
        int r  = i >> 4;
        int c4 = i & 15;
        float4 v = make_float4(0.f, 0.f, 0.f, 0.f);
        if (row0 + r < n) v = ((const float4*)X)[(size_t)(row0 + r) * 16 + c4];
        Xs[r][c4 * 4 + 0] = v.x; Xs[r][c4 * 4 + 1] = v.y;
        Xs[r][c4 * 4 + 2] = v.z; Xs[r][c4 * 4 + 3] = v.w;
    }
    __syncthreads();

    const int rt = t >> 4;    // 0..7  -> rows rt*8 .. rt*8+7
    const int ct = t & 15;    // 0..15 -> cols ct*4 .. ct*4+3

    unsigned long long acc[8][2];
    #pragma unroll
    for (int r = 0; r < 8; r++) { acc[r][0] = 0ull; acc[r][1] = 0ull; }

    #pragma unroll
    for (int k = 0; k < 64; k += 2) {
        ulonglong2 w0 = *(const ulonglong2*)&Ws[k    ][ct * 4];
        ulonglong2 w1 = *(const ulonglong2*)&Ws[k + 1][ct * 4];
        #pragma unroll
        for (int r = 0; r < 8; r++) {
            float2 a2 = *(const float2*)&Xs[rt * 8 + r][k];
            unsigned int a0u = __float_as_uint(a2.x);
            unsigned int a1u = __float_as_uint(a2.y);
            unsigned long long pa0, pa1;
            asm("mov.b64 %0, {%1,%1};" : "=l"(pa0) : "r"(a0u));
            asm("mov.b64 %0, {%1,%1};" : "=l"(pa1) : "r"(a1u));
            asm("fma.rn.f32x2 %0, %1, %2, %0;" : "+l"(acc[r][0]) : "l"(pa0), "l"(w0.x));
            asm("fma.rn.f32x2 %0, %1, %2, %0;" : "+l"(acc[r][1]) : "l"(pa0), "l"(w0.y));
            asm("fma.rn.f32x2 %0, %1, %2, %0;" : "+l"(acc[r][0]) : "l"(pa1), "l"(w1.x));
            asm("fma.rn.f32x2 %0, %1, %2, %0;" : "+l"(acc[r][1]) : "l"(pa1), "l"(w1.y));
        }
    }

    #pragma unroll
    for (int r = 0; r < 8; r++) {
        int row = row0 + rt * 8 + r;
        if (row < n) {
            float4 o;
            o.x = __uint_as_float((unsigned int)(acc[r][0]      ));
            o.y = __uint_as_float((unsigned int)(acc[r][0] >> 32));
            o.z = __uint_as_float((unsigned int)(acc[r][1]      ));
            o.w = __uint_as_float((unsigned int)(acc[r][1] >> 32));
            if (addBias) {
                o.x += bias[ct * 4 + 0]; o.y += bias[ct * 4 + 1];
                o.z += bias[ct * 4 + 2]; o.w += bias[ct * 4 + 3];
            }
            ((float4*)Y)[(size_t)row * 16 + ct] = o;
        }
    }
}

// ---------------- aggregation: one warp per destination node -----------------
// out[i] = relu( sum_{src in CSR[i]} h[src] * dinv[src]*dinv[i]  + b )
__global__ void __launch_bounds__(256) k_agg(
    const float* __restrict__ h, const float* __restrict__ bias,
    float* __restrict__ out, int n, int doRelu)
{
    int w    = (blockIdx.x * blockDim.x + threadIdx.x) >> 5;
    int lane = threadIdx.x & 31;
    if (w >= n) return;

    const float di = g_dinv[w];
    const int s = g_off[w];
    const int e = s + g_deg[w];
    const float2* __restrict__ h2 = (const float2*)h;

    float ax = 0.f, ay = 0.f;
    for (int p = s; p < e; ++p) {
        int   src = __ldg(&g_csr[p]);
        float wt  = di * __ldg(&g_dinv[src]);
        float2 v  = __ldg(&h2[(size_t)src * 32 + lane]);
        ax = fmaf(v.x, wt, ax);
        ay = fmaf(v.y, wt, ay);
    }
    ax += bias[2 * lane];
    ay += bias[2 * lane + 1];
    if (doRelu) { ax = fmaxf(ax, 0.f); ay = fmaxf(ay, 0.f); }
    ((float2*)out)[(size_t)w * 32 + lane] = make_float2(ax, ay);
}

// ---------------- launch -----------------------------------------------------
extern "C" void kernel_launch(void* const* d_in, const int* in_sizes, int n_in,
                              void* d_out, int out_size)
{
    const float*     x    = (const float*)d_in[0];
    const int*       ei32 = (const int*)d_in[1];        // [2, E], dtype detected
    const long long* ei64 = (const long long*)d_in[1];
    // d_in[2] = batch (unused by the reference outputs)
    const float* W0 = (const float*)d_in[3];
    const float* b0 = (const float*)d_in[4];
    const float* W1 = (const float*)d_in[5];
    const float* b1 = (const float*)d_in[6];
    const float* W2 = (const float*)d_in[7];
    const float* b2 = (const float*)d_in[8];
    const float* Wl = (const float*)d_in[9];
    const float* bl = (const float*)d_in[10];

    const int n = in_sizes[0] / HD;       // 100000
    const int E = in_sizes[1] / 2;        // 800000

    float* out1 = (float*)d_out;                        // relu'd GCN output
    const bool haveTwo = (out_size >= 2 * n * HD);
    float* out2 = (float*)d_out + (size_t)n * HD;       // linear head

    float* tmp;  cudaGetSymbolAddress((void**)&tmp,  g_tmp);
    float* bufA; cudaGetSymbolAddress((void**)&bufA, g_bufA);

    const int T = 256;
    // 0) detect edge dtype (int32 vs int64) on-device
    k_detect<<<1, 32>>>(ei64, n);
    // 1) CSR build
    k_init_deg<<<(n + T - 1) / T, T>>>(n);
    k_count  <<<(E + T - 1) / T, T>>>(ei32, ei64, E);
    const int nscan = (n + 511) / 512;
    k_scanA<<<nscan, 512>>>(n);
    k_scanB<<<1, 32>>>(nscan);
    k_scanC<<<(n + T - 1) / T, T>>>(n);
    k_fill <<<(E + n + T - 1) / T, T>>>(ei32, ei64, E, n);

    const int gemmBlocks = (n + 63) / 64;
    const int aggBlocks  = (n * 32 + T - 1) / T;

    // 2) layer 1: h = x@W0 ; agg+b0+relu -> bufA
    k_gemm64<<<gemmBlocks, 128>>>(x, W0, nullptr, tmp, n, 0);
    k_agg   <<<aggBlocks, T>>>(tmp, b0, bufA, n, 1);
    // 3) layer 2
    k_gemm64<<<gemmBlocks, 128>>>(bufA, W1, nullptr, tmp, n, 0);
    k_agg   <<<aggBlocks, T>>>(tmp, b1, bufA, n, 1);
    // 4) layer 3 -> first half of output
    k_gemm64<<<gemmBlocks, 128>>>(bufA, W2, nullptr, tmp, n, 0);
    k_agg   <<<aggBlocks, T>>>(tmp, b2, out1, n, 1);
    // 5) linear head -> second half
    if (haveTwo)
        k_gemm64<<<gemmBlocks, 128>>>(out1, Wl, bl, out2, n, 1);
}